// round 3
// baseline (speedup 1.0000x reference)
#include <cuda_runtime.h>

#define CO 256
#define CI 256
#define SS 57      // effective max dilated kernel length
#define NW 12      // number of (k,d) combos
#define HEAD 28    // SS - (SS+1)/2

struct WPtrs { const float* w[NW]; };

// KD order = product(KS=[3,5,7,9], DS=[1,3,7])
__device__ __constant__ const int c_K[NW] = {3,3,3, 5,5,5, 7,7,7, 9,9,9};
__device__ __constant__ const int c_D[NW] = {1,3,7, 1,3,7, 1,3,7, 1,3,7};

// coef = softmax(alpha + gumbels); log_softmax drops (shift-invariant).
// Tiny (12 exps) — computed inline where needed, scalar-replicated.
__device__ __forceinline__ void softmax12(const float* __restrict__ alpha,
                                          const float* __restrict__ gum,
                                          float* coef) {
    float l[NW];
    float m = -1e30f;
    #pragma unroll
    for (int i = 0; i < NW; i++) {
        l[i] = alpha[i] + gum[i];
        m = fmaxf(m, l[i]);
    }
    float s = 0.0f;
    #pragma unroll
    for (int i = 0; i < NW; i++) {
        l[i] = expf(l[i] - m);
        s += l[i];
    }
    const float inv = 1.0f / s;
    #pragma unroll
    for (int i = 0; i < NW; i++) coef[i] = l[i] * inv;
}

// acc[s] = sum_i coef[i] * dilate(w_i, d_i) padded to SS, at position s
__device__ __forceinline__ float acc_at(const WPtrs& wp, const float* coef,
                                        unsigned row, int s) {
    float a = 0.0f;
    #pragma unroll
    for (int i = 0; i < NW; i++) {
        const int k = c_K[i];
        const int d = c_D[i];
        const int L = d * (k - 1) + 1;
        const int pl = (SS - L) >> 1;          // left pad
        const int t = s - pl;
        if (t >= 0 && t < L && (t % d) == 0)
            a += coef[i] * __ldg(&wp.w[i][row * k + t / d]);
    }
    return a;
}

#define ZROWS 16   // rows per zerofill block

// Disjoint regions per row (requires N % 64 == 0, N >= 128):
//   head   [0, 32)        : scatter family   (values + pad zeros)
//   inner  [32, N-32)     : zerofill family  (pure zeros)
//   tail   [N-32, N)      : scatter family
__global__ void __launch_bounds__(256)
fused_kernel(WPtrs wp,
             const float* __restrict__ alpha,
             const float* __restrict__ gum,
             float* __restrict__ out,
             int N, int nZeroBlocks) {
    if ((int)blockIdx.x < nZeroBlocks) {
        // ---- zerofill: 16 rows/block, 16 threads/row, 15 STG.128 each ----
        const int t   = threadIdx.x;
        const unsigned row = blockIdx.x * ZROWS + (t >> 4);
        const int u   = t & 15;
        float4* p = reinterpret_cast<float4*>(out + (size_t)row * (unsigned)N + 32) + u;
        const int iters = (N - 64) >> 6;       // float4 slots / 16 lanes
        const float4 z = make_float4(0.f, 0.f, 0.f, 0.f);
        #pragma unroll 15
        for (int k = 0; k < iters; k++) p[k * 16] = z;
    } else {
        // ---- scatter: warp per row ----
        __shared__ float sh[8][64];
        const int b = blockIdx.x - nZeroBlocks;
        const int w = threadIdx.x >> 5;
        const int l = threadIdx.x & 31;
        const unsigned row = (unsigned)b * 8u + (unsigned)w;
        float* s = sh[w];

        float coef[NW];
        softmax12(alpha, gum, coef);

        s[l] = acc_at(wp, coef, row, l);                       // s in [0,32)
        if (l < SS - 32) s[l + 32] = acc_at(wp, coef, row, l + 32);  // [32,57)
        __syncwarp();

        if (l < 16) {
            float* o = out + (size_t)row * (unsigned)N;
            float4 v;
            int j0;
            if (l < 8) {                       // head: j0 in [0,28]
                j0 = l << 2;
                v.x = (j0     <= HEAD) ? s[HEAD - j0]     : 0.f;
                v.y = (j0 + 1 <= HEAD) ? s[HEAD - j0 - 1] : 0.f;
                v.z = (j0 + 2 <= HEAD) ? s[HEAD - j0 - 2] : 0.f;
                v.w = (j0 + 3 <= HEAD) ? s[HEAD - j0 - 3] : 0.f;
            } else {                           // tail: j0 in [N-32, N-4]
                j0 = N - 64 + (l << 2);
                const int hi = N - HEAD;
                v.x = (j0     >= hi) ? s[N + HEAD - j0]     : 0.f;
                v.y = (j0 + 1 >= hi) ? s[N + HEAD - j0 - 1] : 0.f;
                v.z = (j0 + 2 >= hi) ? s[N + HEAD - j0 - 2] : 0.f;
                v.w = (j0 + 3 >= hi) ? s[N + HEAD - j0 - 3] : 0.f;
            }
            *reinterpret_cast<float4*>(o + j0) = v;
        }
    }
}

// Fallback for N not multiple of 64 (not expected: N=1024)
__global__ void __launch_bounds__(256)
multiconv_perm_fallback(WPtrs wp,
                        const float* __restrict__ alpha,
                        const float* __restrict__ gum,
                        float* __restrict__ out, int N) {
    __shared__ float sacc[SS];
    __shared__ float scoef[NW];
    const int tid = threadIdx.x;
    const unsigned row = blockIdx.x;
    if (tid == 0) softmax12(alpha, gum, scoef);
    __syncthreads();
    if (tid < SS) sacc[tid] = acc_at(wp, scoef, row, tid);
    __syncthreads();
    const size_t base = (size_t)row * (unsigned)N;
    const int hi = N - HEAD;
    for (int j = tid; j < N; j += 256) {
        out[base + j] = (j <= HEAD) ? sacc[HEAD - j]
                      : ((j >= hi) ? sacc[N + HEAD - j] : 0.0f);
    }
}

extern "C" void kernel_launch(void* const* d_in, const int* in_sizes, int n_in,
                              void* d_out, int out_size) {
    WPtrs wp;
    for (int i = 0; i < NW; i++) wp.w[i] = (const float*)d_in[i];
    const float* alpha = (const float*)d_in[12];
    const float* gum   = (const float*)d_in[13];
    const int N = out_size / (CO * CI);   // input_size, recovered host-side

    float* out = (float*)d_out;
    if ((N % 64) == 0 && N >= 128) {
        const int nZero    = (CO * CI) / ZROWS;  // 4096
        const int nScatter = (CO * CI) / 8;      // 8192
        fused_kernel<<<nZero + nScatter, 256>>>(wp, alpha, gum, out, N, nZero);
    } else {
        multiconv_perm_fallback<<<CO * CI, 256>>>(wp, alpha, gum, out, N);
    }
}

// round 4
// speedup vs baseline: 1.3746x; 1.3746x over previous
#include <cuda_runtime.h>

#define CO 256
#define CI 256
#define SS 57      // effective max dilated kernel length
#define NW 12      // number of (k,d) combos
#define HEAD 28    // SS - (SS+1)/2

struct WPtrs { const float* w[NW]; };

// KD order = product(KS=[3,5,7,9], DS=[1,3,7])
__device__ __constant__ const int c_K[NW] = {3,3,3, 5,5,5, 7,7,7, 9,9,9};
__device__ __constant__ const int c_D[NW] = {1,3,7, 1,3,7, 1,3,7, 1,3,7};

// coef = softmax(alpha + gumbels); log_softmax drops (shift-invariant).
__device__ __forceinline__ void softmax12(const float* __restrict__ alpha,
                                          const float* __restrict__ gum,
                                          float* coef) {
    float l[NW];
    float m = -1e30f;
    #pragma unroll
    for (int i = 0; i < NW; i++) {
        l[i] = alpha[i] + gum[i];
        m = fmaxf(m, l[i]);
    }
    float s = 0.0f;
    #pragma unroll
    for (int i = 0; i < NW; i++) {
        l[i] = __expf(l[i] - m);
        s += l[i];
    }
    const float inv = 1.0f / s;
    #pragma unroll
    for (int i = 0; i < NW; i++) coef[i] = l[i] * inv;
}

#define ZROWS 16          // rows per zerofill block
#define NSCAT_BLOCKS (CO * CI / 256)   // 256: one thread per row

// Row structure (N % 64 == 0, N >= 128):
//   head line  [0, 32)      : scatter family (23-nonzero pattern + zeros)
//   interior   [32, N-32)   : zerofill family (pure zeros)
//   tail line  [N-32, N)    : scatter family
// Regions are disjoint -> no ordering needed, single kernel, two families.
__global__ void __launch_bounds__(256)
fused_kernel(WPtrs wp,
             const float* __restrict__ alpha,
             const float* __restrict__ gum,
             float* __restrict__ out,
             int N) {
    if (blockIdx.x < NSCAT_BLOCKS) {
        // ================= scatter: ONE THREAD PER ROW, straight-line =======
        const unsigned row = blockIdx.x * 256u + threadIdx.x;

        float C[NW];
        softmax12(alpha, gum, C);

        // Load all 72 taps for this row (weights are L2-resident: 18.9 MB)
        float a[3], b[3], c[3], d[5], e[5], f[5], g[7], h[7], p[7];
        float q[9], r10[9], s9[9];
        {
            const float* w0  = wp.w[0]  + row * 3u;
            const float* w1  = wp.w[1]  + row * 3u;
            const float* w2  = wp.w[2]  + row * 3u;
            const float* w3  = wp.w[3]  + row * 5u;
            const float* w4  = wp.w[4]  + row * 5u;
            const float* w5  = wp.w[5]  + row * 5u;
            const float* w6  = wp.w[6]  + row * 7u;
            const float* w7  = wp.w[7]  + row * 7u;
            const float* w8  = wp.w[8]  + row * 7u;
            const float* w9  = wp.w[9]  + row * 9u;
            const float* w10 = wp.w[10] + row * 9u;
            const float* w11 = wp.w[11] + row * 9u;
            #pragma unroll
            for (int t = 0; t < 3; t++) { a[t]=__ldg(w0+t); b[t]=__ldg(w1+t); c[t]=__ldg(w2+t); }
            #pragma unroll
            for (int t = 0; t < 5; t++) { d[t]=__ldg(w3+t); e[t]=__ldg(w4+t); f[t]=__ldg(w5+t); }
            #pragma unroll
            for (int t = 0; t < 7; t++) { g[t]=__ldg(w6+t); h[t]=__ldg(w7+t); p[t]=__ldg(w8+t); }
            #pragma unroll
            for (int t = 0; t < 9; t++) { q[t]=__ldg(w9+t); r10[t]=__ldg(w10+t); s9[t]=__ldg(w11+t); }
        }

        // 23 nonzero acc positions (tap->s map resolved at compile time):
        const float A0  = C[11]*s9[0];
        const float A7  = C[8]*p[0] + C[11]*s9[1];
        const float A14 = C[5]*f[0] + C[8]*p[1] + C[11]*s9[2];
        const float A16 = C[10]*r10[0];
        const float A19 = C[7]*h[0] + C[10]*r10[1];
        const float A21 = C[2]*c[0] + C[5]*f[1] + C[8]*p[2] + C[11]*s9[3];
        const float A22 = C[4]*e[0] + C[7]*h[1] + C[10]*r10[2];
        const float A24 = C[9]*q[0];
        const float A25 = C[1]*b[0] + C[4]*e[1] + C[6]*g[0] + C[7]*h[2] + C[9]*q[1] + C[10]*r10[3];
        const float A26 = C[3]*d[0] + C[6]*g[1] + C[9]*q[2];
        const float A27 = C[0]*a[0] + C[3]*d[1] + C[6]*g[2] + C[9]*q[3];
        const float A28 = C[0]*a[1] + C[1]*b[1] + C[2]*c[1] + C[3]*d[2] + C[4]*e[2] + C[5]*f[2]
                        + C[6]*g[3] + C[7]*h[3] + C[8]*p[3] + C[9]*q[4] + C[10]*r10[4] + C[11]*s9[4];
        const float A29 = C[0]*a[2] + C[3]*d[3] + C[6]*g[4] + C[9]*q[5];
        const float A30 = C[3]*d[4] + C[6]*g[5] + C[9]*q[6];
        const float A31 = C[1]*b[2] + C[4]*e[3] + C[6]*g[6] + C[7]*h[4] + C[9]*q[7] + C[10]*r10[5];
        const float A32 = C[9]*q[8];
        const float A34 = C[4]*e[4] + C[7]*h[5] + C[10]*r10[6];
        const float A35 = C[2]*c[2] + C[5]*f[3] + C[8]*p[4] + C[11]*s9[5];
        const float A37 = C[7]*h[6] + C[10]*r10[7];
        const float A40 = C[10]*r10[8];
        const float A42 = C[5]*f[4] + C[8]*p[5] + C[11]*s9[6];
        const float A49 = C[8]*p[6] + C[11]*s9[7];
        const float A56 = C[11]*s9[8];

        float* o = out + (size_t)row * (unsigned)N;
        float4* oh = reinterpret_cast<float4*>(o);            // head line
        float4* ot = reinterpret_cast<float4*>(o + N - 32);   // tail line

        // head: out[j] = acc[28-j] (j<=28), else 0
        oh[0] = make_float4(A28, A27, A26, A25);
        oh[1] = make_float4(A24, 0.f, A22, A21);
        oh[2] = make_float4(0.f, A19, 0.f, 0.f);
        oh[3] = make_float4(A16, 0.f, A14, 0.f);
        oh[4] = make_float4(0.f, 0.f, 0.f, 0.f);
        oh[5] = make_float4(0.f, A7, 0.f, 0.f);
        oh[6] = make_float4(0.f, 0.f, 0.f, 0.f);
        oh[7] = make_float4(A0, 0.f, 0.f, 0.f);
        // tail: out[N-32+v] = acc[60-v] (v>=4), else 0
        ot[0] = make_float4(0.f, 0.f, 0.f, 0.f);
        ot[1] = make_float4(A56, 0.f, 0.f, 0.f);
        ot[2] = make_float4(0.f, 0.f, 0.f, A49);
        ot[3] = make_float4(0.f, 0.f, 0.f, 0.f);
        ot[4] = make_float4(0.f, 0.f, A42, 0.f);
        ot[5] = make_float4(A40, 0.f, 0.f, A37);
        ot[6] = make_float4(0.f, A35, A34, 0.f);
        ot[7] = make_float4(A32, A31, A30, A29);
    } else {
        // ================= zerofill: 16 rows/block, 16 threads/row ==========
        const int t = threadIdx.x;
        const unsigned row = (blockIdx.x - NSCAT_BLOCKS) * ZROWS + (t >> 4);
        const int u = t & 15;
        float4* pz = reinterpret_cast<float4*>(out + (size_t)row * (unsigned)N + 32) + u;
        const int iters = (N - 64) >> 6;
        const float4 z = make_float4(0.f, 0.f, 0.f, 0.f);
        #pragma unroll 15
        for (int k = 0; k < iters; k++) pz[k * 16] = z;
    }
}

// Fallback for N not multiple of 64 (not expected: N=1024)
__global__ void __launch_bounds__(256)
multiconv_perm_fallback(WPtrs wp,
                        const float* __restrict__ alpha,
                        const float* __restrict__ gum,
                        float* __restrict__ out, int N) {
    __shared__ float sacc[SS];
    __shared__ float scoef[NW];
    const int tid = threadIdx.x;
    const unsigned row = blockIdx.x;
    if (tid == 0) softmax12(alpha, gum, scoef);
    __syncthreads();
    if (tid < SS) {
        float acc = 0.0f;
        #pragma unroll
        for (int i = 0; i < NW; i++) {
            const int k = c_K[i];
            const int d = c_D[i];
            const int L = d * (k - 1) + 1;
            const int pl = (SS - L) >> 1;
            const int tt = tid - pl;
            if (tt >= 0 && tt < L && (tt % d) == 0)
                acc += scoef[i] * __ldg(&wp.w[i][row * k + tt / d]);
        }
        sacc[tid] = acc;
    }
    __syncthreads();
    const size_t base = (size_t)row * (unsigned)N;
    const int hi = N - HEAD;
    for (int j = tid; j < N; j += 256) {
        out[base + j] = (j <= HEAD) ? sacc[HEAD - j]
                      : ((j >= hi) ? sacc[N + HEAD - j] : 0.0f);
    }
}

extern "C" void kernel_launch(void* const* d_in, const int* in_sizes, int n_in,
                              void* d_out, int out_size) {
    WPtrs wp;
    for (int i = 0; i < NW; i++) wp.w[i] = (const float*)d_in[i];
    const float* alpha = (const float*)d_in[12];
    const float* gum   = (const float*)d_in[13];
    const int N = out_size / (CO * CI);   // input_size, recovered host-side

    float* out = (float*)d_out;
    if ((N % 64) == 0 && N >= 128) {
        const int nZero = (CO * CI) / ZROWS;              // 4096
        fused_kernel<<<NSCAT_BLOCKS + nZero, 256>>>(wp, alpha, gum, out, N);
    } else {
        multiconv_perm_fallback<<<CO * CI, 256>>>(wp, alpha, gum, out, N);
    }
}

// round 5
// speedup vs baseline: 1.4280x; 1.0388x over previous
#include <cuda_runtime.h>

#define CO 256
#define CI 256
#define SS 57      // effective max dilated kernel length
#define NW 12      // number of (k,d) combos
#define HEAD 28    // SS - (SS+1)/2

struct WPtrs { const float* w[NW]; };

// KD order = product(KS=[3,5,7,9], DS=[1,3,7])
__device__ __constant__ const int c_K[NW] = {3,3,3, 5,5,5, 7,7,7, 9,9,9};
__device__ __constant__ const int c_D[NW] = {1,3,7, 1,3,7, 1,3,7, 1,3,7};

// coef = softmax(alpha + gumbels); log_softmax drops (shift-invariant).
__device__ __forceinline__ void softmax12(const float* __restrict__ alpha,
                                          const float* __restrict__ gum,
                                          float* coef) {
    float l[NW];
    float m = -1e30f;
    #pragma unroll
    for (int i = 0; i < NW; i++) {
        l[i] = alpha[i] + gum[i];
        m = fmaxf(m, l[i]);
    }
    float s = 0.0f;
    #pragma unroll
    for (int i = 0; i < NW; i++) {
        l[i] = __expf(l[i] - m);
        s += l[i];
    }
    const float inv = 1.0f / s;
    #pragma unroll
    for (int i = 0; i < NW; i++) coef[i] = l[i] * inv;
}

#define ZROWS 16                        // rows per zerofill block
#define NSCAT_BLOCKS (CO * CI / 256)    // one thread per row

// Row structure (N % 64 == 0, N >= 128):
//   head line  [0, 32)      : scatter family (23-nonzero pattern + zeros)
//   interior   [32, N-32)   : zerofill family (pure zeros)
//   tail line  [N-32, N)    : scatter family
// Regions are disjoint -> no ordering needed, single kernel, two families.
// launch_bounds(256, 8): cap regs at 32 so the zerofill family reaches
// 8 CTAs/SM (full 2048 threads); the scatter branch may spill — it is 6%
// of blocks and compute-trivial.
__global__ void __launch_bounds__(256, 8)
fused_kernel(WPtrs wp,
             const float* __restrict__ alpha,
             const float* __restrict__ gum,
             float* __restrict__ out,
             int N) {
    if (blockIdx.x >= NSCAT_BLOCKS) {
        // ================= zerofill: 16 rows/block, 16 threads/row ==========
        const int t = threadIdx.x;
        const unsigned row = (blockIdx.x - NSCAT_BLOCKS) * ZROWS + (t >> 4);
        const int u = t & 15;
        float4* pz = reinterpret_cast<float4*>(out + (size_t)row * (unsigned)N + 32) + u;
        const int iters = (N - 64) >> 6;         // 15 for N=1024
        const float4 z = make_float4(0.f, 0.f, 0.f, 0.f);
        #pragma unroll 15
        for (int k = 0; k < iters; k++) {
            __stcs(pz, z);                       // STG.E.128.CS: evict-first
            pz += 16;
        }
    } else {
        // ================= scatter: ONE THREAD PER ROW, straight-line =======
        const unsigned row = blockIdx.x * 256u + threadIdx.x;

        float C[NW];
        softmax12(alpha, gum, C);

        // Load all 72 taps for this row (weights are L2-resident: 18.9 MB)
        float a[3], b[3], c[3], d[5], e[5], f[5], g[7], h[7], p[7];
        float q[9], r10[9], s9[9];
        {
            const float* w0  = wp.w[0]  + row * 3u;
            const float* w1  = wp.w[1]  + row * 3u;
            const float* w2  = wp.w[2]  + row * 3u;
            const float* w3  = wp.w[3]  + row * 5u;
            const float* w4  = wp.w[4]  + row * 5u;
            const float* w5  = wp.w[5]  + row * 5u;
            const float* w6  = wp.w[6]  + row * 7u;
            const float* w7  = wp.w[7]  + row * 7u;
            const float* w8  = wp.w[8]  + row * 7u;
            const float* w9  = wp.w[9]  + row * 9u;
            const float* w10 = wp.w[10] + row * 9u;
            const float* w11 = wp.w[11] + row * 9u;
            #pragma unroll
            for (int t = 0; t < 3; t++) { a[t]=__ldg(w0+t); b[t]=__ldg(w1+t); c[t]=__ldg(w2+t); }
            #pragma unroll
            for (int t = 0; t < 5; t++) { d[t]=__ldg(w3+t); e[t]=__ldg(w4+t); f[t]=__ldg(w5+t); }
            #pragma unroll
            for (int t = 0; t < 7; t++) { g[t]=__ldg(w6+t); h[t]=__ldg(w7+t); p[t]=__ldg(w8+t); }
            #pragma unroll
            for (int t = 0; t < 9; t++) { q[t]=__ldg(w9+t); r10[t]=__ldg(w10+t); s9[t]=__ldg(w11+t); }
        }

        // 23 nonzero acc positions (tap->s map resolved at compile time):
        const float A0  = C[11]*s9[0];
        const float A7  = C[8]*p[0] + C[11]*s9[1];
        const float A14 = C[5]*f[0] + C[8]*p[1] + C[11]*s9[2];
        const float A16 = C[10]*r10[0];
        const float A19 = C[7]*h[0] + C[10]*r10[1];
        const float A21 = C[2]*c[0] + C[5]*f[1] + C[8]*p[2] + C[11]*s9[3];
        const float A22 = C[4]*e[0] + C[7]*h[1] + C[10]*r10[2];
        const float A24 = C[9]*q[0];
        const float A25 = C[1]*b[0] + C[4]*e[1] + C[6]*g[0] + C[7]*h[2] + C[9]*q[1] + C[10]*r10[3];
        const float A26 = C[3]*d[0] + C[6]*g[1] + C[9]*q[2];
        const float A27 = C[0]*a[0] + C[3]*d[1] + C[6]*g[2] + C[9]*q[3];
        const float A28 = C[0]*a[1] + C[1]*b[1] + C[2]*c[1] + C[3]*d[2] + C[4]*e[2] + C[5]*f[2]
                        + C[6]*g[3] + C[7]*h[3] + C[8]*p[3] + C[9]*q[4] + C[10]*r10[4] + C[11]*s9[4];
        const float A29 = C[0]*a[2] + C[3]*d[3] + C[6]*g[4] + C[9]*q[5];
        const float A30 = C[3]*d[4] + C[6]*g[5] + C[9]*q[6];
        const float A31 = C[1]*b[2] + C[4]*e[3] + C[6]*g[6] + C[7]*h[4] + C[9]*q[7] + C[10]*r10[5];
        const float A32 = C[9]*q[8];
        const float A34 = C[4]*e[4] + C[7]*h[5] + C[10]*r10[6];
        const float A35 = C[2]*c[2] + C[5]*f[3] + C[8]*p[4] + C[11]*s9[5];
        const float A37 = C[7]*h[6] + C[10]*r10[7];
        const float A40 = C[10]*r10[8];
        const float A42 = C[5]*f[4] + C[8]*p[5] + C[11]*s9[6];
        const float A49 = C[8]*p[6] + C[11]*s9[7];
        const float A56 = C[11]*s9[8];

        float* o = out + (size_t)row * (unsigned)N;
        float4* oh = reinterpret_cast<float4*>(o);            // head line
        float4* ot = reinterpret_cast<float4*>(o + N - 32);   // tail line

        // head: out[j] = acc[28-j] (j<=28), else 0
        __stcs(oh + 0, make_float4(A28, A27, A26, A25));
        __stcs(oh + 1, make_float4(A24, 0.f, A22, A21));
        __stcs(oh + 2, make_float4(0.f, A19, 0.f, 0.f));
        __stcs(oh + 3, make_float4(A16, 0.f, A14, 0.f));
        __stcs(oh + 4, make_float4(0.f, 0.f, 0.f, 0.f));
        __stcs(oh + 5, make_float4(0.f, A7, 0.f, 0.f));
        __stcs(oh + 6, make_float4(0.f, 0.f, 0.f, 0.f));
        __stcs(oh + 7, make_float4(A0, 0.f, 0.f, 0.f));
        // tail: out[N-32+v] = acc[60-v] (v>=4), else 0
        __stcs(ot + 0, make_float4(0.f, 0.f, 0.f, 0.f));
        __stcs(ot + 1, make_float4(A56, 0.f, 0.f, 0.f));
        __stcs(ot + 2, make_float4(0.f, 0.f, 0.f, A49));
        __stcs(ot + 3, make_float4(0.f, 0.f, 0.f, 0.f));
        __stcs(ot + 4, make_float4(0.f, 0.f, A42, 0.f));
        __stcs(ot + 5, make_float4(A40, 0.f, 0.f, A37));
        __stcs(ot + 6, make_float4(0.f, A35, A34, 0.f));
        __stcs(ot + 7, make_float4(A32, A31, A30, A29));
    }
}

// Fallback for N not multiple of 64 (not expected: N=1024)
__global__ void __launch_bounds__(256)
multiconv_perm_fallback(WPtrs wp,
                        const float* __restrict__ alpha,
                        const float* __restrict__ gum,
                        float* __restrict__ out, int N) {
    __shared__ float sacc[SS];
    __shared__ float scoef[NW];
    const int tid = threadIdx.x;
    const unsigned row = blockIdx.x;
    if (tid == 0) softmax12(alpha, gum, scoef);
    __syncthreads();
    if (tid < SS) {
        float acc = 0.0f;
        #pragma unroll
        for (int i = 0; i < NW; i++) {
            const int k = c_K[i];
            const int d = c_D[i];
            const int L = d * (k - 1) + 1;
            const int pl = (SS - L) >> 1;
            const int tt = tid - pl;
            if (tt >= 0 && tt < L && (tt % d) == 0)
                acc += scoef[i] * __ldg(&wp.w[i][row * k + tt / d]);
        }
        sacc[tid] = acc;
    }
    __syncthreads();
    const size_t base = (size_t)row * (unsigned)N;
    const int hi = N - HEAD;
    for (int j = tid; j < N; j += 256) {
        out[base + j] = (j <= HEAD) ? sacc[HEAD - j]
                      : ((j >= hi) ? sacc[N + HEAD - j] : 0.0f);
    }
}

extern "C" void kernel_launch(void* const* d_in, const int* in_sizes, int n_in,
                              void* d_out, int out_size) {
    WPtrs wp;
    for (int i = 0; i < NW; i++) wp.w[i] = (const float*)d_in[i];
    const float* alpha = (const float*)d_in[12];
    const float* gum   = (const float*)d_in[13];
    const int N = out_size / (CO * CI);   // input_size, recovered host-side

    float* out = (float*)d_out;
    if ((N % 64) == 0 && N >= 128) {
        const int nZero = (CO * CI) / ZROWS;              // 4096
        fused_kernel<<<NSCAT_BLOCKS + nZero, 256>>>(wp, alpha, gum, out, N);
    } else {
        multiconv_perm_fallback<<<CO * CI, 256>>>(wp, alpha, gum, out, N);
    }
}